// round 2
// baseline (speedup 1.0000x reference)
#include <cuda_runtime.h>
#include <math.h>

// Problem constants (LocalRNN: B=16, L=1024, D=256, ksize=16)
#define B_   16
#define L_   1024
#define D_   256
#define KS_  16
#define G_   768            // 3*D
#define NCH_ (B_ * L_)      // 16384 chains

// Scratch for precomputed input gates: gi[n][g], n in [0,16384), g in [0,768)
__device__ float g_gi[(size_t)NCH_ * G_];   // 50.3 MB, static device scratch

// ---------------------------------------------------------------------------
// Kernel 1: GI = x @ W_ih^T + b_ih      (16384 x 768 GEMM, K=256)
// Tile 64(M) x 64(N), K-chunks of 16, TM=TN=4 register tile.
// ---------------------------------------------------------------------------
__global__ __launch_bounds__(256) void gi_gemm_kernel(
    const float* __restrict__ x,
    const float* __restrict__ Wih,
    const float* __restrict__ bih)
{
    __shared__ float As[16][68];
    __shared__ float Bs[16][68];

    const int mt  = blockIdx.x * 64;   // chain tile
    const int nt  = blockIdx.y * 64;   // gate tile
    const int tid = threadIdx.x;
    const int txx = tid & 15;          // -> j0 = txx*4
    const int tyy = tid >> 4;          // -> m0 = tyy*4

    float acc[4][4];
#pragma unroll
    for (int i = 0; i < 4; i++)
#pragma unroll
        for (int j = 0; j < 4; j++) acc[i][j] = 0.f;

    for (int kt = 0; kt < D_; kt += 16) {
#pragma unroll
        for (int i = 0; i < 4; i++) {
            int idx = i * 256 + tid;
            int m = idx >> 4, k = idx & 15;
            As[k][m] = x[(size_t)(mt + m) * D_ + kt + k];
            Bs[k][m] = Wih[(size_t)(nt + m) * D_ + kt + k];
        }
        __syncthreads();
#pragma unroll
        for (int k = 0; k < 16; k++) {
            float a[4], b[4];
#pragma unroll
            for (int i = 0; i < 4; i++) a[i] = As[k][tyy * 4 + i];
#pragma unroll
            for (int i = 0; i < 4; i++) b[i] = Bs[k][txx * 4 + i];
#pragma unroll
            for (int i = 0; i < 4; i++)
#pragma unroll
                for (int j = 0; j < 4; j++)
                    acc[i][j] = fmaf(a[i], b[j], acc[i][j]);
        }
        __syncthreads();
    }

#pragma unroll
    for (int i = 0; i < 4; i++) {
        int n = mt + tyy * 4 + i;
#pragma unroll
        for (int j = 0; j < 4; j++) {
            int g = nt + txx * 4 + j;
            g_gi[(size_t)n * G_ + g] = acc[i][j] + bih[g];
        }
    }
}

// ---------------------------------------------------------------------------
// Kernel 2: persistent GRU recurrence.
// Each CTA owns 64 consecutive chains for all 16 steps.
// Per step, per gate block g in {r,z,n}:
//   GH[64][256] = H[64][256] @ W_hh[g*256 : (g+1)*256, :]^T   (reg-tiled fp32)
// followed by a fused gate epilogue. H, R, Z tiles in smem; W_hh streamed
// from L2 in 16-wide K slices; gi rows read from g_gi (L2-resident).
//
// Dynamic smem layout (floats):
//   Hs [64*256]        @ 0
//   Rs [64*256]        @ 16384
//   Zs [64*256]        @ 32768
//   Ws [16][260]       @ 49152   (row stride 260 keeps 16B alignment)
//   bih[768]           @ 53312
//   bhh[768]           @ 54080
// total 54848 floats = 219392 B
// ---------------------------------------------------------------------------
#define WS_STRIDE 260
#define RNN_SMEM_FLOATS (49152 + 16 * WS_STRIDE + 768 + 768)
#define RNN_SMEM_BYTES  (RNN_SMEM_FLOATS * 4)

__global__ __launch_bounds__(256, 1) void rnn_kernel(
    const float* __restrict__ Whh,
    const float* __restrict__ bih_g,
    const float* __restrict__ bhh_g,
    float* __restrict__ out)
{
    extern __shared__ float sm[];
    float* Hs  = sm;
    float* Rs  = sm + 16384;
    float* Zs  = sm + 32768;
    float* Ws  = sm + 49152;
    float* bih = sm + 49152 + 16 * WS_STRIDE;
    float* bhh = bih + 768;

    const int tid  = threadIdx.x;
    const int lane = tid & 31;     // j tile: j0 = lane*8   (256 cols)
    const int wrp  = tid >> 5;     // m tile: m0 = wrp*8    (64 rows)
    const int j0   = lane * 8;
    const int m0   = wrp * 8;
    const int n0   = blockIdx.x * 64;

    for (int i = tid; i < 16384; i += 256) Hs[i] = 0.f;
    for (int i = tid; i < 768; i += 256) { bih[i] = bih_g[i]; bhh[i] = bhh_g[i]; }
    __syncthreads();

    for (int t = 0; t < KS_; t++) {
        for (int g = 0; g < 3; g++) {
            float acc[8][8];
#pragma unroll
            for (int i = 0; i < 8; i++)
#pragma unroll
                for (int j = 0; j < 8; j++) acc[i][j] = 0.f;

            const float* Wg = Whh + (size_t)g * 256 * D_;

            for (int kt = 0; kt < D_; kt += 16) {
                // Stage W slice: Ws[k][j] = Wg[j][kt+k], j = tid (256 rows)
                const float4* src = (const float4*)(Wg + (size_t)tid * D_ + kt);
#pragma unroll
                for (int i = 0; i < 4; i++) {
                    float4 v = src[i];
                    Ws[(i * 4 + 0) * WS_STRIDE + tid] = v.x;
                    Ws[(i * 4 + 1) * WS_STRIDE + tid] = v.y;
                    Ws[(i * 4 + 2) * WS_STRIDE + tid] = v.z;
                    Ws[(i * 4 + 3) * WS_STRIDE + tid] = v.w;
                }
                __syncthreads();
#pragma unroll
                for (int k = 0; k < 16; k++) {
                    float4 b0 = *(const float4*)(Ws + k * WS_STRIDE + j0);
                    float4 b1 = *(const float4*)(Ws + k * WS_STRIDE + j0 + 4);
                    float b[8] = {b0.x, b0.y, b0.z, b0.w, b1.x, b1.y, b1.z, b1.w};
                    float a[8];
#pragma unroll
                    for (int i = 0; i < 8; i++)
                        a[i] = Hs[(m0 + i) * 256 + kt + k];   // broadcast across lanes
#pragma unroll
                    for (int i = 0; i < 8; i++)
#pragma unroll
                        for (int j = 0; j < 8; j++)
                            acc[i][j] = fmaf(a[i], b[j], acc[i][j]);
                }
                __syncthreads();
            }

            // Fused gate epilogue (each thread owns its (m,j) cells across all
            // three gate blocks, so R/Z need no cross-thread sync; H writes in
            // g==2 are ordered vs. next GEMM reads by the staging barrier).
            const int gb = g * 256;
#pragma unroll
            for (int i = 0; i < 8; i++) {
                const int m  = m0 + i;
                const int n  = n0 + m;
                const int l  = n & (L_ - 1);
                const int lp = l - (KS_ - 1) + t;           // source seq position
                const float* girow = (lp >= 0)
                    ? (g_gi + (size_t)(n - (KS_ - 1) + t) * G_ + gb)
                    : (bih + gb);                            // zero-padded x -> gi = b_ih
#pragma unroll
                for (int j = 0; j < 8; j++) {
                    const int d  = j0 + j;
                    float giv = girow[d];
                    float ghv = acc[i][j] + bhh[gb + d];
                    if (g == 0) {
                        Rs[m * 256 + d] = 1.f / (1.f + expf(-(giv + ghv)));
                    } else if (g == 1) {
                        Zs[m * 256 + d] = 1.f / (1.f + expf(-(giv + ghv)));
                    } else {
                        float r  = Rs[m * 256 + d];
                        float nv = tanhf(giv + r * ghv);
                        float z  = Zs[m * 256 + d];
                        float h  = Hs[m * 256 + d];
                        Hs[m * 256 + d] = (1.f - z) * nv + z * h;
                    }
                }
            }
        }
    }

    __syncthreads();
    // Hs is densely packed [m][d] with stride 256 -> contiguous store
    for (int i = tid; i < 64 * 256; i += 256)
        out[(size_t)n0 * 256 + i] = Hs[i];
}

// ---------------------------------------------------------------------------
// Launch
// ---------------------------------------------------------------------------
extern "C" void kernel_launch(void* const* d_in, const int* in_sizes, int n_in,
                              void* d_out, int out_size)
{
    const float* x    = (const float*)d_in[0];
    const float* Wih  = (const float*)d_in[1];
    const float* Whh  = (const float*)d_in[2];
    const float* bih  = (const float*)d_in[3];
    const float* bhh  = (const float*)d_in[4];
    // d_in[5] = ksize (compile-time 16)
    float* out = (float*)d_out;

    dim3 grid1(NCH_ / 64, G_ / 64);
    gi_gemm_kernel<<<grid1, 256>>>(x, Wih, bih);

    cudaFuncSetAttribute(rnn_kernel,
                         cudaFuncAttributeMaxDynamicSharedMemorySize,
                         RNN_SMEM_BYTES);
    rnn_kernel<<<NCH_ / 64, 256, RNN_SMEM_BYTES>>>(Whh, bih, bhh, out);
}

// round 3
// speedup vs baseline: 1.0011x; 1.0011x over previous
#include <cuda_runtime.h>
#include <math.h>

// Problem constants (LocalRNN: B=16, L=1024, D=256, ksize=16)
#define B_   16
#define L_   1024
#define D_   256
#define KS_  16
#define G_   768            // 3*D
#define NCH_ (B_ * L_)      // 16384 chains

// Scratch for precomputed input gates: gi[n][g], n in [0,16384), g in [0,768)
__device__ float g_gi[(size_t)NCH_ * G_];   // 50.3 MB, static device scratch

// ---------------------------------------------------------------------------
// Kernel 1: GI = x @ W_ih^T + b_ih      (16384 x 768 GEMM, K=256)
// Tile 64(M) x 64(N), K-chunks of 16, TM=TN=4 register tile.
// ---------------------------------------------------------------------------
__global__ __launch_bounds__(256) void gi_gemm_kernel(
    const float* __restrict__ x,
    const float* __restrict__ Wih,
    const float* __restrict__ bih)
{
    __shared__ float As[16][68];
    __shared__ float Bs[16][68];

    const int mt  = blockIdx.x * 64;   // chain tile
    const int nt  = blockIdx.y * 64;   // gate tile
    const int tid = threadIdx.x;
    const int txx = tid & 15;          // -> j0 = txx*4
    const int tyy = tid >> 4;          // -> m0 = tyy*4

    float acc[4][4];
#pragma unroll
    for (int i = 0; i < 4; i++)
#pragma unroll
        for (int j = 0; j < 4; j++) acc[i][j] = 0.f;

    for (int kt = 0; kt < D_; kt += 16) {
#pragma unroll
        for (int i = 0; i < 4; i++) {
            int idx = i * 256 + tid;
            int m = idx >> 4, k = idx & 15;
            As[k][m] = x[(size_t)(mt + m) * D_ + kt + k];
            Bs[k][m] = Wih[(size_t)(nt + m) * D_ + kt + k];
        }
        __syncthreads();
#pragma unroll
        for (int k = 0; k < 16; k++) {
            float a[4], b[4];
#pragma unroll
            for (int i = 0; i < 4; i++) a[i] = As[k][tyy * 4 + i];
#pragma unroll
            for (int i = 0; i < 4; i++) b[i] = Bs[k][txx * 4 + i];
#pragma unroll
            for (int i = 0; i < 4; i++)
#pragma unroll
                for (int j = 0; j < 4; j++)
                    acc[i][j] = fmaf(a[i], b[j], acc[i][j]);
        }
        __syncthreads();
    }

#pragma unroll
    for (int i = 0; i < 4; i++) {
        int n = mt + tyy * 4 + i;
#pragma unroll
        for (int j = 0; j < 4; j++) {
            int g = nt + txx * 4 + j;
            g_gi[(size_t)n * G_ + g] = acc[i][j] + bih[g];
        }
    }
}

// ---------------------------------------------------------------------------
// Kernel 2: persistent GRU recurrence.
// Each CTA owns 64 consecutive chains for all 16 steps.
// Per step, per gate block g in {r,z,n}:
//   GH[64][256] = H[64][256] @ W_hh[g*256 : (g+1)*256, :]^T   (reg-tiled fp32)
// followed by a fused gate epilogue. H, R, Z tiles in smem; W_hh streamed
// from L2 in 16-wide K slices; gi rows read from g_gi (L2-resident).
//
// Dynamic smem layout (floats):
//   Hs [64*256]        @ 0
//   Rs [64*256]        @ 16384
//   Zs [64*256]        @ 32768
//   Ws [16][260]       @ 49152   (row stride 260 keeps 16B alignment)
//   bih[768]           @ 53312
//   bhh[768]           @ 54080
// total 54848 floats = 219392 B
// ---------------------------------------------------------------------------
#define WS_STRIDE 260
#define RNN_SMEM_FLOATS (49152 + 16 * WS_STRIDE + 768 + 768)
#define RNN_SMEM_BYTES  (RNN_SMEM_FLOATS * 4)

__global__ __launch_bounds__(256, 1) void rnn_kernel(
    const float* __restrict__ Whh,
    const float* __restrict__ bih_g,
    const float* __restrict__ bhh_g,
    float* __restrict__ out)
{
    extern __shared__ float sm[];
    float* Hs  = sm;
    float* Rs  = sm + 16384;
    float* Zs  = sm + 32768;
    float* Ws  = sm + 49152;
    float* bih = sm + 49152 + 16 * WS_STRIDE;
    float* bhh = bih + 768;

    const int tid  = threadIdx.x;
    const int lane = tid & 31;     // j tile: j0 = lane*8   (256 cols)
    const int wrp  = tid >> 5;     // m tile: m0 = wrp*8    (64 rows)
    const int j0   = lane * 8;
    const int m0   = wrp * 8;
    const int n0   = blockIdx.x * 64;

    for (int i = tid; i < 16384; i += 256) Hs[i] = 0.f;
    for (int i = tid; i < 768; i += 256) { bih[i] = bih_g[i]; bhh[i] = bhh_g[i]; }
    __syncthreads();

    for (int t = 0; t < KS_; t++) {
        for (int g = 0; g < 3; g++) {
            float acc[8][8];
#pragma unroll
            for (int i = 0; i < 8; i++)
#pragma unroll
                for (int j = 0; j < 8; j++) acc[i][j] = 0.f;

            const float* Wg = Whh + (size_t)g * 256 * D_;

            for (int kt = 0; kt < D_; kt += 16) {
                // Stage W slice: Ws[k][j] = Wg[j][kt+k], j = tid (256 rows)
                const float4* src = (const float4*)(Wg + (size_t)tid * D_ + kt);
#pragma unroll
                for (int i = 0; i < 4; i++) {
                    float4 v = src[i];
                    Ws[(i * 4 + 0) * WS_STRIDE + tid] = v.x;
                    Ws[(i * 4 + 1) * WS_STRIDE + tid] = v.y;
                    Ws[(i * 4 + 2) * WS_STRIDE + tid] = v.z;
                    Ws[(i * 4 + 3) * WS_STRIDE + tid] = v.w;
                }
                __syncthreads();
#pragma unroll
                for (int k = 0; k < 16; k++) {
                    float4 b0 = *(const float4*)(Ws + k * WS_STRIDE + j0);
                    float4 b1 = *(const float4*)(Ws + k * WS_STRIDE + j0 + 4);
                    float b[8] = {b0.x, b0.y, b0.z, b0.w, b1.x, b1.y, b1.z, b1.w};
                    float a[8];
#pragma unroll
                    for (int i = 0; i < 8; i++)
                        a[i] = Hs[(m0 + i) * 256 + kt + k];   // broadcast across lanes
#pragma unroll
                    for (int i = 0; i < 8; i++)
#pragma unroll
                        for (int j = 0; j < 8; j++)
                            acc[i][j] = fmaf(a[i], b[j], acc[i][j]);
                }
                __syncthreads();
            }

            // Fused gate epilogue (each thread owns its (m,j) cells across all
            // three gate blocks, so R/Z need no cross-thread sync; H writes in
            // g==2 are ordered vs. next GEMM reads by the staging barrier).
            const int gb = g * 256;
#pragma unroll
            for (int i = 0; i < 8; i++) {
                const int m  = m0 + i;
                const int n  = n0 + m;
                const int l  = n & (L_ - 1);
                const int lp = l - (KS_ - 1) + t;           // source seq position
                const float* girow = (lp >= 0)
                    ? (g_gi + (size_t)(n - (KS_ - 1) + t) * G_ + gb)
                    : (bih + gb);                            // zero-padded x -> gi = b_ih
#pragma unroll
                for (int j = 0; j < 8; j++) {
                    const int d  = j0 + j;
                    float giv = girow[d];
                    float ghv = acc[i][j] + bhh[gb + d];
                    if (g == 0) {
                        Rs[m * 256 + d] = 1.f / (1.f + expf(-(giv + ghv)));
                    } else if (g == 1) {
                        Zs[m * 256 + d] = 1.f / (1.f + expf(-(giv + ghv)));
                    } else {
                        float r  = Rs[m * 256 + d];
                        float nv = tanhf(giv + r * ghv);
                        float z  = Zs[m * 256 + d];
                        float h  = Hs[m * 256 + d];
                        Hs[m * 256 + d] = (1.f - z) * nv + z * h;
                    }
                }
            }
        }
    }

    __syncthreads();
    // Hs is densely packed [m][d] with stride 256 -> contiguous store
    for (int i = tid; i < 64 * 256; i += 256)
        out[(size_t)n0 * 256 + i] = Hs[i];
}

// ---------------------------------------------------------------------------
// Launch
// ---------------------------------------------------------------------------
extern "C" void kernel_launch(void* const* d_in, const int* in_sizes, int n_in,
                              void* d_out, int out_size)
{
    const float* x    = (const float*)d_in[0];
    const float* Wih  = (const float*)d_in[1];
    const float* Whh  = (const float*)d_in[2];
    const float* bih  = (const float*)d_in[3];
    const float* bhh  = (const float*)d_in[4];
    // d_in[5] = ksize (compile-time 16)
    float* out = (float*)d_out;

    dim3 grid1(NCH_ / 64, G_ / 64);
    gi_gemm_kernel<<<grid1, 256>>>(x, Wih, bih);

    cudaFuncSetAttribute(rnn_kernel,
                         cudaFuncAttributeMaxDynamicSharedMemorySize,
                         RNN_SMEM_BYTES);
    rnn_kernel<<<NCH_ / 64, 256, RNN_SMEM_BYTES>>>(Whh, bih, bhh, out);
}